// round 1
// baseline (speedup 1.0000x reference)
#include <cuda_runtime.h>
#include <math.h>

#define NN 50000
#define NE 800000
#define NODE_F 5
#define MAP_F 32
#define XUF 37
#define FULLF 28
#define RNN 20
#define RNN_E 8
#define LAT 32

// ---------------- scratch (device globals; no allocations) ----------------
__device__ float g_xu[NN * XUF];      // [N,37] concat(x,u)
__device__ float g_full[NN * FULLF];  // [N,28] concat(node_hist, edge_hist)
__device__ float g_msum[NN * LAT];    // phase-1 message sums
__device__ float g_esum[NN * LAT];    // phase-2 message sums
__device__ int   g_cnt[NN];           // in-degree counts (shared by both phases)

__device__ __forceinline__ float sigm(float v) { return 1.f / (1.f + expf(-v)); }

// ---------------- K1: build xu, node-history LSTM, zero accumulators ------
__global__ void __launch_bounds__(256) k1_node(
    const float* __restrict__ x, const float* __restrict__ u,
    const float* __restrict__ hh, const float* __restrict__ hc,
    const float* __restrict__ Wih, const float* __restrict__ Whh,
    const float* __restrict__ bih, const float* __restrict__ bhh,
    float* __restrict__ outh, float* __restrict__ outc)
{
    __shared__ float sW[80 * 37];
    __shared__ float sU[80 * 20];
    __shared__ float sb[80];
    for (int i = threadIdx.x; i < 80 * 37; i += 256) sW[i] = Wih[i];
    for (int i = threadIdx.x; i < 80 * 20; i += 256) sU[i] = Whh[i];
    for (int i = threadIdx.x; i < 80; i += 256) sb[i] = bih[i] + bhh[i];
    __syncthreads();

    int n = blockIdx.x * 256 + threadIdx.x;
    if (n >= NN) return;

    float xu[37];
#pragma unroll
    for (int k = 0; k < 5; k++)  xu[k] = x[n * 5 + k];
#pragma unroll
    for (int k = 0; k < 32; k++) xu[5 + k] = u[n * 32 + k];
#pragma unroll
    for (int k = 0; k < 37; k++) g_xu[n * 37 + k] = xu[k];

    float h[20];
#pragma unroll
    for (int j = 0; j < 20; j++) h[j] = hh[n * 20 + j];

    // zero the aggregation buffers for this node (K2/K4 atomics come later)
#pragma unroll
    for (int k = 0; k < 32; k++) { g_msum[n * 32 + k] = 0.f; g_esum[n * 32 + k] = 0.f; }
    g_cnt[n] = 0;

    for (int q = 0; q < 20; q++) {
        float gi = sb[q], gf = sb[20 + q], gg = sb[40 + q], go = sb[60 + q];
        const float* wi = &sW[q * 37];
        const float* wf = &sW[(20 + q) * 37];
        const float* wg = &sW[(40 + q) * 37];
        const float* wo = &sW[(60 + q) * 37];
#pragma unroll
        for (int k = 0; k < 37; k++) {
            float v = xu[k];
            gi += v * wi[k]; gf += v * wf[k]; gg += v * wg[k]; go += v * wo[k];
        }
        const float* ui = &sU[q * 20];
        const float* uf = &sU[(20 + q) * 20];
        const float* ug = &sU[(40 + q) * 20];
        const float* uo = &sU[(60 + q) * 20];
#pragma unroll
        for (int j = 0; j < 20; j++) {
            float v = h[j];
            gi += v * ui[j]; gf += v * uf[j]; gg += v * ug[j]; go += v * uo[j];
        }
        float c0 = hc[n * 20 + q];
        float cn = sigm(gf) * c0 + sigm(gi) * tanhf(gg);
        float hn = sigm(go) * tanhf(cn);
        outh[n * 20 + q] = hn;
        outc[n * 20 + q] = cn;
        g_full[n * 28 + q] = hn;
    }
}

// ---------------- edge MLP (templated on input width) ---------------------
// IN=78: feat = g_xu (F=37), accum = g_msum, counts updated
// IN=60: feat = g_full (F=28), accum = g_esum
template <int IN>
__global__ void __launch_bounds__(128) edge_mlp(
    const int* __restrict__ ei, const float* __restrict__ ea,
    const float* __restrict__ W1, const float* __restrict__ b1,
    const float* __restrict__ W2, const float* __restrict__ b2,
    const float* __restrict__ feat, float* __restrict__ accum, int doCnt)
{
    __shared__ float sW1[IN * 64];
    __shared__ float sW2[64 * 32];
    __shared__ float sb1[64];
    __shared__ float sb2[32];
    for (int i = threadIdx.x; i < IN * 64; i += 128) sW1[i] = W1[i];
    for (int i = threadIdx.x; i < 64 * 32; i += 128) sW2[i] = W2[i];
    if (threadIdx.x < 64) sb1[threadIdx.x] = b1[threadIdx.x];
    if (threadIdx.x < 32) sb2[threadIdx.x] = b2[threadIdx.x];
    __syncthreads();

    int e = blockIdx.x * 128 + threadIdx.x;
    if (e >= NE) return;

    const int F = (IN - 4) / 2;
    int r = ei[e];
    int c = ei[NE + e];

    float in[IN];
    const float* ps = feat + (long)r * F;
    const float* pd = feat + (long)c * F;
#pragma unroll
    for (int k = 0; k < F; k++) in[k]     = __ldg(ps + k);
#pragma unroll
    for (int k = 0; k < F; k++) in[F + k] = __ldg(pd + k);
    float4 e4 = *(const float4*)(ea + (long)e * 4);
    in[2 * F + 0] = e4.x; in[2 * F + 1] = e4.y; in[2 * F + 2] = e4.z; in[2 * F + 3] = e4.w;

    float out[32];
#pragma unroll
    for (int o = 0; o < 32; o++) out[o] = sb2[o];

    for (int jb = 0; jb < 64; jb += 8) {
        float h[8];
#pragma unroll
        for (int q = 0; q < 8; q++) h[q] = sb1[jb + q];
#pragma unroll
        for (int k = 0; k < IN; k++) {
            float v = in[k];
            float4 wa = *(const float4*)&sW1[k * 64 + jb];
            float4 wb = *(const float4*)&sW1[k * 64 + jb + 4];
            h[0] += v * wa.x; h[1] += v * wa.y; h[2] += v * wa.z; h[3] += v * wa.w;
            h[4] += v * wb.x; h[5] += v * wb.y; h[6] += v * wb.z; h[7] += v * wb.w;
        }
#pragma unroll
        for (int q = 0; q < 8; q++) {
            float hv = fmaxf(h[q], 0.f);
            const float* w = &sW2[(jb + q) * 32];
#pragma unroll
            for (int ob = 0; ob < 32; ob += 4) {
                float4 w4 = *(const float4*)&w[ob];
                out[ob + 0] += hv * w4.x; out[ob + 1] += hv * w4.y;
                out[ob + 2] += hv * w4.z; out[ob + 3] += hv * w4.w;
            }
        }
    }

    float* dst = accum + (long)c * 32;
#pragma unroll
    for (int ob = 0; ob < 32; ob += 4) {
        asm volatile("red.global.add.v4.f32 [%0], {%1, %2, %3, %4};"
                     :: "l"(dst + ob),
                        "f"(out[ob + 0]), "f"(out[ob + 1]),
                        "f"(out[ob + 2]), "f"(out[ob + 3])
                     : "memory");
    }
    if (doCnt) atomicAdd(&g_cnt[c], 1);
}

// ---------------- K3: segment mean + edge-history LSTM --------------------
__global__ void __launch_bounds__(256) k3_edge_lstm(
    const float* __restrict__ hh, const float* __restrict__ hc,
    const float* __restrict__ Wih, const float* __restrict__ Whh,
    const float* __restrict__ bih, const float* __restrict__ bhh,
    float* __restrict__ outh, float* __restrict__ outc)
{
    __shared__ float sW[32 * 32];
    __shared__ float sU[32 * 8];
    __shared__ float sb[32];
    for (int i = threadIdx.x; i < 32 * 32; i += 256) sW[i] = Wih[i];
    for (int i = threadIdx.x; i < 32 * 8; i += 256)  sU[i] = Whh[i];
    for (int i = threadIdx.x; i < 32; i += 256) sb[i] = bih[i] + bhh[i];
    __syncthreads();

    int n = blockIdx.x * 256 + threadIdx.x;
    if (n >= NN) return;

    float inv = 1.f / fmaxf((float)g_cnt[n], 1.f);
    float a[32];
#pragma unroll
    for (int k = 0; k < 32; k++) a[k] = g_msum[n * 32 + k] * inv;
    float h[8];
#pragma unroll
    for (int j = 0; j < 8; j++) h[j] = hh[n * 8 + j];

    for (int q = 0; q < 8; q++) {
        float gi = sb[q], gf = sb[8 + q], gg = sb[16 + q], go = sb[24 + q];
#pragma unroll
        for (int k = 0; k < 32; k++) {
            float v = a[k];
            gi += v * sW[q * 32 + k];
            gf += v * sW[(8 + q) * 32 + k];
            gg += v * sW[(16 + q) * 32 + k];
            go += v * sW[(24 + q) * 32 + k];
        }
#pragma unroll
        for (int j = 0; j < 8; j++) {
            float v = h[j];
            gi += v * sU[q * 8 + j];
            gf += v * sU[(8 + q) * 8 + j];
            gg += v * sU[(16 + q) * 8 + j];
            go += v * sU[(24 + q) * 8 + j];
        }
        float c0 = hc[n * 8 + q];
        float cn = sigm(gf) * c0 + sigm(gi) * tanhf(gg);
        float hn = sigm(go) * tanhf(cn);
        outh[n * 8 + q] = hn;
        outc[n * 8 + q] = cn;
        g_full[n * 28 + 20 + q] = hn;
    }
}

// ---------------- K5: segment mean + output node MLP ----------------------
__global__ void __launch_bounds__(256) k5_out(
    const float* __restrict__ Wn1, const float* __restrict__ bn1,
    const float* __restrict__ Wn2, const float* __restrict__ bn2,
    float* __restrict__ out)
{
    __shared__ float sW1[60 * 64];
    __shared__ float sW2[64 * 4];
    __shared__ float sb1[64];
    __shared__ float sb2[4];
    for (int i = threadIdx.x; i < 60 * 64; i += 256) sW1[i] = Wn1[i];
    for (int i = threadIdx.x; i < 64 * 4; i += 256)  sW2[i] = Wn2[i];
    if (threadIdx.x < 64) sb1[threadIdx.x] = bn1[threadIdx.x];
    if (threadIdx.x < 4)  sb2[threadIdx.x] = bn2[threadIdx.x];
    __syncthreads();

    int n = blockIdx.x * 256 + threadIdx.x;
    if (n >= NN) return;

    float in[60];
#pragma unroll
    for (int k = 0; k < 28; k++) in[k] = g_full[n * 28 + k];
    float inv = 1.f / fmaxf((float)g_cnt[n], 1.f);
#pragma unroll
    for (int k = 0; k < 32; k++) in[28 + k] = g_esum[n * 32 + k] * inv;

    float o0 = sb2[0], o1 = sb2[1], o2 = sb2[2], o3 = sb2[3];
    for (int jb = 0; jb < 64; jb += 8) {
        float h[8];
#pragma unroll
        for (int q = 0; q < 8; q++) h[q] = sb1[jb + q];
#pragma unroll
        for (int k = 0; k < 60; k++) {
            float v = in[k];
            float4 wa = *(const float4*)&sW1[k * 64 + jb];
            float4 wb = *(const float4*)&sW1[k * 64 + jb + 4];
            h[0] += v * wa.x; h[1] += v * wa.y; h[2] += v * wa.z; h[3] += v * wa.w;
            h[4] += v * wb.x; h[5] += v * wb.y; h[6] += v * wb.z; h[7] += v * wb.w;
        }
#pragma unroll
        for (int q = 0; q < 8; q++) {
            float hv = fmaxf(h[q], 0.f);
            float4 w4 = *(const float4*)&sW2[(jb + q) * 4];
            o0 += hv * w4.x; o1 += hv * w4.y; o2 += hv * w4.z; o3 += hv * w4.w;
        }
    }
    float4 r; r.x = o0; r.y = o1; r.z = o2; r.w = o3;
    *(float4*)(out + (long)n * 4) = r;
}

// ---------------- launch ---------------------------------------------------
extern "C" void kernel_launch(void* const* d_in, const int* in_sizes, int n_in,
                              void* d_out, int out_size)
{
    const float* x     = (const float*)d_in[0];
    const float* u     = (const float*)d_in[1];
    const int*   ei    = (const int*)  d_in[2];
    const float* ea    = (const float*)d_in[3];
    const float* hnh   = (const float*)d_in[4];
    const float* hnc   = (const float*)d_in[5];
    const float* heh   = (const float*)d_in[6];
    const float* hec   = (const float*)d_in[7];
    const float* Wih_n = (const float*)d_in[8];
    const float* Whh_n = (const float*)d_in[9];
    const float* bih_n = (const float*)d_in[10];
    const float* bhh_n = (const float*)d_in[11];
    const float* Wih_e = (const float*)d_in[12];
    const float* Whh_e = (const float*)d_in[13];
    const float* bih_e = (const float*)d_in[14];
    const float* bhh_e = (const float*)d_in[15];
    const float* We1 = (const float*)d_in[16];
    const float* be1 = (const float*)d_in[17];
    const float* We2 = (const float*)d_in[18];
    const float* be2 = (const float*)d_in[19];
    const float* Wo1 = (const float*)d_in[20];
    const float* bo1 = (const float*)d_in[21];
    const float* Wo2 = (const float*)d_in[22];
    const float* bo2 = (const float*)d_in[23];
    const float* Wn1 = (const float*)d_in[24];
    const float* bn1 = (const float*)d_in[25];
    const float* Wn2 = (const float*)d_in[26];
    const float* bn2 = (const float*)d_in[27];

    float* out    = (float*)d_out;
    float* out_y  = out;                       // [N,4]
    float* out_nh = out_y + (long)NN * 4;      // node_hist [N,20]
    float* out_nc = out_nh + (long)NN * RNN;   // node_c    [N,20]
    float* out_eh = out_nc + (long)NN * RNN;   // edge_hist [N,8]
    float* out_ec = out_eh + (long)NN * RNN_E; // edge_c    [N,8]

    void *p_xu, *p_full, *p_msum, *p_esum;
    cudaGetSymbolAddress(&p_xu,   g_xu);
    cudaGetSymbolAddress(&p_full, g_full);
    cudaGetSymbolAddress(&p_msum, g_msum);
    cudaGetSymbolAddress(&p_esum, g_esum);

    int nb = (NN + 255) / 256;
    int eb = (NE + 127) / 128;

    k1_node<<<nb, 256>>>(x, u, hnh, hnc, Wih_n, Whh_n, bih_n, bhh_n, out_nh, out_nc);
    edge_mlp<78><<<eb, 128>>>(ei, ea, We1, be1, We2, be2,
                              (const float*)p_xu, (float*)p_msum, 1);
    k3_edge_lstm<<<nb, 256>>>(heh, hec, Wih_e, Whh_e, bih_e, bhh_e, out_eh, out_ec);
    edge_mlp<60><<<eb, 128>>>(ei, ea, Wo1, bo1, Wo2, bo2,
                              (const float*)p_full, (float*)p_esum, 0);
    k5_out<<<nb, 256>>>(Wn1, bn1, Wn2, bn2, out_y);
}

// round 5
// speedup vs baseline: 1.3934x; 1.3934x over previous
#include <cuda_runtime.h>
#include <math.h>

#define NN 50000
#define NE 800000
#define XUF 37
#define XUP 40      // padded row stride for g_xu (float4-aligned gathers)
#define FULLF 28
#define RNN 20
#define RNN_E 8
#define LAT 32

// ---------------- scratch (device globals; no allocations) ----------------
__device__ float g_xu[NN * XUP];      // [N,40] concat(x,u) + pad
__device__ float g_full[NN * FULLF];  // [N,28] concat(node_hist, edge_hist)
__device__ float g_msum[NN * LAT];
__device__ float g_esum[NN * LAT];
__device__ int   g_cnt[NN];

__device__ __forceinline__ float sigm(float v) { return 1.f / (1.f + expf(-v)); }

// ---------------- K1: build xu, node-history LSTM, zero accumulators ------
__global__ void __launch_bounds__(256) k1_node(
    const float* __restrict__ x, const float* __restrict__ u,
    const float* __restrict__ hh, const float* __restrict__ hc,
    const float* __restrict__ Wih, const float* __restrict__ Whh,
    const float* __restrict__ bih, const float* __restrict__ bhh,
    float* __restrict__ outh, float* __restrict__ outc)
{
    __shared__ float sW[80 * 37];
    __shared__ float sU[80 * 20];
    __shared__ float sb[80];
    for (int i = threadIdx.x; i < 80 * 37; i += 256) sW[i] = Wih[i];
    for (int i = threadIdx.x; i < 80 * 20; i += 256) sU[i] = Whh[i];
    for (int i = threadIdx.x; i < 80; i += 256) sb[i] = bih[i] + bhh[i];
    __syncthreads();

    int n = blockIdx.x * 256 + threadIdx.x;
    if (n >= NN) return;

    float xu[37];
#pragma unroll
    for (int k = 0; k < 5; k++)  xu[k] = x[n * 5 + k];
#pragma unroll
    for (int k = 0; k < 32; k++) xu[5 + k] = u[n * 32 + k];
#pragma unroll
    for (int k = 0; k < 37; k++) g_xu[n * XUP + k] = xu[k];
    g_xu[n * XUP + 37] = 0.f; g_xu[n * XUP + 38] = 0.f; g_xu[n * XUP + 39] = 0.f;

    float h[20];
#pragma unroll
    for (int j = 0; j < 20; j++) h[j] = hh[n * 20 + j];

#pragma unroll
    for (int k = 0; k < 32; k++) { g_msum[n * 32 + k] = 0.f; g_esum[n * 32 + k] = 0.f; }
    g_cnt[n] = 0;

    for (int q = 0; q < 20; q++) {
        float gi = sb[q], gf = sb[20 + q], gg = sb[40 + q], go = sb[60 + q];
        const float* wi = &sW[q * 37];
        const float* wf = &sW[(20 + q) * 37];
        const float* wg = &sW[(40 + q) * 37];
        const float* wo = &sW[(60 + q) * 37];
#pragma unroll
        for (int k = 0; k < 37; k++) {
            float v = xu[k];
            gi += v * wi[k]; gf += v * wf[k]; gg += v * wg[k]; go += v * wo[k];
        }
        const float* ui = &sU[q * 20];
        const float* uf = &sU[(20 + q) * 20];
        const float* ug = &sU[(40 + q) * 20];
        const float* uo = &sU[(60 + q) * 20];
#pragma unroll
        for (int j = 0; j < 20; j++) {
            float v = h[j];
            gi += v * ui[j]; gf += v * uf[j]; gg += v * ug[j]; go += v * uo[j];
        }
        float c0 = hc[n * 20 + q];
        float cn = sigm(gf) * c0 + sigm(gi) * tanhf(gg);
        float hn = sigm(go) * tanhf(cn);
        outh[n * 20 + q] = hn;
        outc[n * 20 + q] = cn;
        g_full[n * 28 + q] = hn;
    }
}

// ---------------- edge GEMM kernel ----------------------------------------
// Block = 128 edges. Stage inputs k-major in smem, register-blocked GEMM.
// IN: input width (78 or 60); F: per-node feature width; FP: padded row stride
// of feat; NV4: float4 loads per row.
template <int IN, int F, int FP, int NV4>
__global__ void __launch_bounds__(128) edge_gemm(
    const int* __restrict__ ei, const float* __restrict__ ea,
    const float* __restrict__ W1, const float* __restrict__ b1,
    const float* __restrict__ W2, const float* __restrict__ b2,
    const float* __restrict__ feat, float* __restrict__ accum, int doCnt)
{
    extern __shared__ float smem[];
    const int HROWS = (IN > 64) ? IN : 64;
    float* sIn = smem;                    // [HROWS][128], aliased as sH[64][128]
    float* sW1 = sIn + HROWS * 128;       // [IN][64]
    float* sW2 = sW1 + IN * 64;           // [64][32]
    __shared__ float sb1[64];
    __shared__ float sb2[32];
    __shared__ int   sCol[128];

    const int tid = threadIdx.x;

    // --- cooperative weight/bias load (float4) ---
    {
        const float4* w1s = (const float4*)W1;
        float4* w1d = (float4*)sW1;
        for (int i = tid; i < IN * 16; i += 128) w1d[i] = w1s[i];
        const float4* w2s = (const float4*)W2;
        float4* w2d = (float4*)sW2;
        for (int i = tid; i < 64 * 8; i += 128) w2d[i] = w2s[i];
        if (tid < 64) sb1[tid] = b1[tid];
        if (tid < 32) sb2[tid] = b2[tid];
    }

    // --- gather: one thread per edge ---
    {
        int e = blockIdx.x * 128 + tid;
        int r = ei[e];
        int c = ei[NE + e];
        sCol[tid] = c;
        if (doCnt) atomicAdd(&g_cnt[c], 1);

        const float4* ps = (const float4*)(feat + (long)r * FP);
        const float4* pd = (const float4*)(feat + (long)c * FP);
#pragma unroll
        for (int j = 0; j < NV4; j++) {
            float4 v = __ldg(ps + j);
            int k = 4 * j;
            if (k + 0 < F) sIn[(k + 0) * 128 + tid] = v.x;
            if (k + 1 < F) sIn[(k + 1) * 128 + tid] = v.y;
            if (k + 2 < F) sIn[(k + 2) * 128 + tid] = v.z;
            if (k + 3 < F) sIn[(k + 3) * 128 + tid] = v.w;
        }
#pragma unroll
        for (int j = 0; j < NV4; j++) {
            float4 v = __ldg(pd + j);
            int k = 4 * j;
            if (k + 0 < F) sIn[(F + k + 0) * 128 + tid] = v.x;
            if (k + 1 < F) sIn[(F + k + 1) * 128 + tid] = v.y;
            if (k + 2 < F) sIn[(F + k + 2) * 128 + tid] = v.z;
            if (k + 3 < F) sIn[(F + k + 3) * 128 + tid] = v.w;
        }
        float4 e4 = __ldg((const float4*)(ea + (long)e * 4));
        sIn[(2 * F + 0) * 128 + tid] = e4.x;
        sIn[(2 * F + 1) * 128 + tid] = e4.y;
        sIn[(2 * F + 2) * 128 + tid] = e4.z;
        sIn[(2 * F + 3) * 128 + tid] = e4.w;
    }
    __syncthreads();

    // --- GEMM1: [128 edges] x [IN] x [64 hidden], 8x8 register tile ---
    const int er = tid & 15;   // edge group: edges er*8 .. er*8+7
    const int hr = tid >> 4;   // hidden group: hidden hr*8 .. hr*8+7
    float acc[8][8];
#pragma unroll
    for (int i = 0; i < 8; i++)
#pragma unroll
        for (int q = 0; q < 8; q++) acc[i][q] = sb1[hr * 8 + q];

#pragma unroll 6
    for (int k = 0; k < IN; k++) {
        float4 a0 = *(const float4*)&sIn[k * 128 + er * 8];
        float4 a1 = *(const float4*)&sIn[k * 128 + er * 8 + 4];
        float4 w0 = *(const float4*)&sW1[k * 64 + hr * 8];
        float4 w1 = *(const float4*)&sW1[k * 64 + hr * 8 + 4];
        float a[8] = {a0.x, a0.y, a0.z, a0.w, a1.x, a1.y, a1.z, a1.w};
        float w[8] = {w0.x, w0.y, w0.z, w0.w, w1.x, w1.y, w1.z, w1.w};
#pragma unroll
        for (int i = 0; i < 8; i++)
#pragma unroll
            for (int q = 0; q < 8; q++) acc[i][q] += a[i] * w[q];
    }
    __syncthreads();

    // --- ReLU + store hidden to smem (aliases sIn) ---
    float* sH = sIn;  // [64][128]
#pragma unroll
    for (int q = 0; q < 8; q++) {
        int j = hr * 8 + q;
        float4 v0, v1;
        v0.x = fmaxf(acc[0][q], 0.f); v0.y = fmaxf(acc[1][q], 0.f);
        v0.z = fmaxf(acc[2][q], 0.f); v0.w = fmaxf(acc[3][q], 0.f);
        v1.x = fmaxf(acc[4][q], 0.f); v1.y = fmaxf(acc[5][q], 0.f);
        v1.z = fmaxf(acc[6][q], 0.f); v1.w = fmaxf(acc[7][q], 0.f);
        *(float4*)&sH[j * 128 + er * 8] = v0;
        *(float4*)&sH[j * 128 + er * 8 + 4] = v1;
    }
    __syncthreads();

    // --- GEMM2: [128 edges] x [64] x [32 out], 8x4 register tile ---
    const int orr = tid >> 4;  // out group: cols orr*4 .. orr*4+3
    float acc2[8][4];
#pragma unroll
    for (int i = 0; i < 8; i++)
#pragma unroll
        for (int q = 0; q < 4; q++) acc2[i][q] = sb2[orr * 4 + q];

#pragma unroll 4
    for (int k = 0; k < 64; k++) {
        float4 a0 = *(const float4*)&sH[k * 128 + er * 8];
        float4 a1 = *(const float4*)&sH[k * 128 + er * 8 + 4];
        float4 w  = *(const float4*)&sW2[k * 32 + orr * 4];
        float a[8] = {a0.x, a0.y, a0.z, a0.w, a1.x, a1.y, a1.z, a1.w};
        float wv[4] = {w.x, w.y, w.z, w.w};
#pragma unroll
        for (int i = 0; i < 8; i++)
#pragma unroll
            for (int q = 0; q < 4; q++) acc2[i][q] += a[i] * wv[q];
    }

    // --- scatter-add ---
#pragma unroll
    for (int i = 0; i < 8; i++) {
        int c = sCol[er * 8 + i];
        float* dst = accum + (long)c * 32 + orr * 4;
        asm volatile("red.global.add.v4.f32 [%0], {%1, %2, %3, %4};"
                     :: "l"(dst),
                        "f"(acc2[i][0]), "f"(acc2[i][1]),
                        "f"(acc2[i][2]), "f"(acc2[i][3])
                     : "memory");
    }
}

// ---------------- K3: segment mean + edge-history LSTM --------------------
__global__ void __launch_bounds__(256) k3_edge_lstm(
    const float* __restrict__ hh, const float* __restrict__ hc,
    const float* __restrict__ Wih, const float* __restrict__ Whh,
    const float* __restrict__ bih, const float* __restrict__ bhh,
    float* __restrict__ outh, float* __restrict__ outc)
{
    __shared__ float sW[32 * 32];
    __shared__ float sU[32 * 8];
    __shared__ float sb[32];
    for (int i = threadIdx.x; i < 32 * 32; i += 256) sW[i] = Wih[i];
    for (int i = threadIdx.x; i < 32 * 8; i += 256)  sU[i] = Whh[i];
    for (int i = threadIdx.x; i < 32; i += 256) sb[i] = bih[i] + bhh[i];
    __syncthreads();

    int n = blockIdx.x * 256 + threadIdx.x;
    if (n >= NN) return;

    float inv = 1.f / fmaxf((float)g_cnt[n], 1.f);
    float a[32];
#pragma unroll
    for (int k = 0; k < 32; k++) a[k] = g_msum[n * 32 + k] * inv;
    float h[8];
#pragma unroll
    for (int j = 0; j < 8; j++) h[j] = hh[n * 8 + j];

    for (int q = 0; q < 8; q++) {
        float gi = sb[q], gf = sb[8 + q], gg = sb[16 + q], go = sb[24 + q];
#pragma unroll
        for (int k = 0; k < 32; k++) {
            float v = a[k];
            gi += v * sW[q * 32 + k];
            gf += v * sW[(8 + q) * 32 + k];
            gg += v * sW[(16 + q) * 32 + k];
            go += v * sW[(24 + q) * 32 + k];
        }
#pragma unroll
        for (int j = 0; j < 8; j++) {
            float v = h[j];
            gi += v * sU[q * 8 + j];
            gf += v * sU[(8 + q) * 8 + j];
            gg += v * sU[(16 + q) * 8 + j];
            go += v * sU[(24 + q) * 8 + j];
        }
        float c0 = hc[n * 8 + q];
        float cn = sigm(gf) * c0 + sigm(gi) * tanhf(gg);
        float hn = sigm(go) * tanhf(cn);
        outh[n * 8 + q] = hn;
        outc[n * 8 + q] = cn;
        g_full[n * 28 + 20 + q] = hn;
    }
}

// ---------------- K5: segment mean + output node MLP ----------------------
__global__ void __launch_bounds__(256) k5_out(
    const float* __restrict__ Wn1, const float* __restrict__ bn1,
    const float* __restrict__ Wn2, const float* __restrict__ bn2,
    float* __restrict__ out)
{
    __shared__ float sW1[60 * 64];
    __shared__ float sW2[64 * 4];
    __shared__ float sb1[64];
    __shared__ float sb2[4];
    for (int i = threadIdx.x; i < 60 * 64; i += 256) sW1[i] = Wn1[i];
    for (int i = threadIdx.x; i < 64 * 4; i += 256)  sW2[i] = Wn2[i];
    if (threadIdx.x < 64) sb1[threadIdx.x] = bn1[threadIdx.x];
    if (threadIdx.x < 4)  sb2[threadIdx.x] = bn2[threadIdx.x];
    __syncthreads();

    int n = blockIdx.x * 256 + threadIdx.x;
    if (n >= NN) return;

    float in[60];
#pragma unroll
    for (int k = 0; k < 28; k++) in[k] = g_full[n * 28 + k];
    float inv = 1.f / fmaxf((float)g_cnt[n], 1.f);
#pragma unroll
    for (int k = 0; k < 32; k++) in[28 + k] = g_esum[n * 32 + k] * inv;

    float o0 = sb2[0], o1 = sb2[1], o2 = sb2[2], o3 = sb2[3];
    for (int jb = 0; jb < 64; jb += 8) {
        float h[8];
#pragma unroll
        for (int q = 0; q < 8; q++) h[q] = sb1[jb + q];
#pragma unroll
        for (int k = 0; k < 60; k++) {
            float v = in[k];
            float4 wa = *(const float4*)&sW1[k * 64 + jb];
            float4 wb = *(const float4*)&sW1[k * 64 + jb + 4];
            h[0] += v * wa.x; h[1] += v * wa.y; h[2] += v * wa.z; h[3] += v * wa.w;
            h[4] += v * wb.x; h[5] += v * wb.y; h[6] += v * wb.z; h[7] += v * wb.w;
        }
#pragma unroll
        for (int q = 0; q < 8; q++) {
            float hv = fmaxf(h[q], 0.f);
            float4 w4 = *(const float4*)&sW2[(jb + q) * 4];
            o0 += hv * w4.x; o1 += hv * w4.y; o2 += hv * w4.z; o3 += hv * w4.w;
        }
    }
    float4 r; r.x = o0; r.y = o1; r.z = o2; r.w = o3;
    *(float4*)(out + (long)n * 4) = r;
}

// ---------------- launch ---------------------------------------------------
extern "C" void kernel_launch(void* const* d_in, const int* in_sizes, int n_in,
                              void* d_out, int out_size)
{
    const float* x     = (const float*)d_in[0];
    const float* u     = (const float*)d_in[1];
    const int*   ei    = (const int*)  d_in[2];
    const float* ea    = (const float*)d_in[3];
    const float* hnh   = (const float*)d_in[4];
    const float* hnc   = (const float*)d_in[5];
    const float* heh   = (const float*)d_in[6];
    const float* hec   = (const float*)d_in[7];
    const float* Wih_n = (const float*)d_in[8];
    const float* Whh_n = (const float*)d_in[9];
    const float* bih_n = (const float*)d_in[10];
    const float* bhh_n = (const float*)d_in[11];
    const float* Wih_e = (const float*)d_in[12];
    const float* Whh_e = (const float*)d_in[13];
    const float* bih_e = (const float*)d_in[14];
    const float* bhh_e = (const float*)d_in[15];
    const float* We1 = (const float*)d_in[16];
    const float* be1 = (const float*)d_in[17];
    const float* We2 = (const float*)d_in[18];
    const float* be2 = (const float*)d_in[19];
    const float* Wo1 = (const float*)d_in[20];
    const float* bo1 = (const float*)d_in[21];
    const float* Wo2 = (const float*)d_in[22];
    const float* bo2 = (const float*)d_in[23];
    const float* Wn1 = (const float*)d_in[24];
    const float* bn1 = (const float*)d_in[25];
    const float* Wn2 = (const float*)d_in[26];
    const float* bn2 = (const float*)d_in[27];

    float* out    = (float*)d_out;
    float* out_y  = out;
    float* out_nh = out_y + (long)NN * 4;
    float* out_nc = out_nh + (long)NN * RNN;
    float* out_eh = out_nc + (long)NN * RNN;
    float* out_ec = out_eh + (long)NN * RNN_E;

    void *p_xu, *p_full, *p_msum, *p_esum;
    cudaGetSymbolAddress(&p_xu,   g_xu);
    cudaGetSymbolAddress(&p_full, g_full);
    cudaGetSymbolAddress(&p_msum, g_msum);
    cudaGetSymbolAddress(&p_esum, g_esum);

    const int smem1 = (78 * 128 + 78 * 64 + 64 * 32) * 4;  // 68096
    const int smem2 = (64 * 128 + 60 * 64 + 64 * 32) * 4;  // 56320
    cudaFuncSetAttribute(edge_gemm<78, 37, XUP, 10>,
                         cudaFuncAttributeMaxDynamicSharedMemorySize, smem1);
    cudaFuncSetAttribute(edge_gemm<60, 28, 28, 7>,
                         cudaFuncAttributeMaxDynamicSharedMemorySize, smem2);

    int nb = (NN + 255) / 256;
    int eb = NE / 128;  // 6250, exact

    k1_node<<<nb, 256>>>(x, u, hnh, hnc, Wih_n, Whh_n, bih_n, bhh_n, out_nh, out_nc);
    edge_gemm<78, 37, XUP, 10><<<eb, 128, smem1>>>(
        ei, ea, We1, be1, We2, be2, (const float*)p_xu, (float*)p_msum, 1);
    k3_edge_lstm<<<nb, 256>>>(heh, hec, Wih_e, Whh_e, bih_e, bhh_e, out_eh, out_ec);
    edge_gemm<60, 28, 28, 7><<<eb, 128, smem2>>>(
        ei, ea, Wo1, bo1, Wo2, bo2, (const float*)p_full, (float*)p_esum, 0);
    k5_out<<<nb, 256>>>(Wn1, bn1, Wn2, bn2, out_y);
}